// round 3
// baseline (speedup 1.0000x reference)
#include <cuda_runtime.h>

#define NPT 4096
#define BSZ 4
#define FEATD 64
#define MT 64
#define ROWS 64
#define THREADS 256

// Packed dual-fp32 FMA (sm_100+). Lane0/lane1 accumulate even/odd m partials.
__device__ __forceinline__ unsigned long long ffma2(unsigned long long a,
                                                    unsigned long long b,
                                                    unsigned long long c) {
    unsigned long long d;
    asm("fma.rn.f32x2 %0, %1, %2, %3;" : "=l"(d) : "l"(a), "l"(b), "l"(c));
    return d;
}

__device__ __forceinline__ float fsqrt_approx(float x) {
    float y;
    asm("sqrt.approx.f32 %0, %1;" : "=f"(y) : "f"(x));
    return y;  // sqrt.approx(+0) == +0, matches reference's safe-sqrt exactly
}

__global__ __launch_bounds__(THREADS, 2)
void fused_relpos_kernel(const float* __restrict__ pos,
                         const float* __restrict__ W,
                         const float* __restrict__ bias,
                         const float* __restrict__ gamma,
                         const float* __restrict__ beta,
                         float* __restrict__ out) {
    __shared__ float q_s[ROWS * 3];        // query positions for this CTA's rows
    __shared__ float d_s[ROWS * MT];       // dist tile [row][m]
    __shared__ float w_s[FEATD * MT];      // W tile [f][m], column XOR-swizzled

    const int t = threadIdx.x;
    const int b = blockIdx.y;
    const int row0 = blockIdx.x * ROWS;

    const int tx = t & 15;                 // feature group (4 feats each)
    const int ty = t >> 4;                 // row group (4 rows each)
    const int f0 = tx << 2;
    const int r0 = ty << 2;
    const int sw = (tx & 7) << 2;          // read-side swizzle for w_s

    const float* posb = pos + (size_t)b * NPT * 3;
    for (int i = t; i < ROWS * 3; i += THREADS)
        q_s[i] = posb[row0 * 3 + i];

    // fill-phase per-thread constants
    const int mmf = t & 63;                // dist fill: fixed column
    const int rb  = t >> 6;                // dist fill: row base (0..3)
    const int f_ld = t >> 2;               // W fill: feature row (0..63)
    const int mmc  = (t & 3) << 4;         // W fill: column base
    const int swz  = ((f_ld >> 2) & 7) << 2;  // write-side swizzle

    unsigned long long acc[4][4];          // f32x2 accumulators (even/odd m)
#pragma unroll
    for (int j = 0; j < 4; j++)
#pragma unroll
        for (int i = 0; i < 4; i++) acc[j][i] = 0ULL;

    for (int m0 = 0; m0 < NPT; m0 += MT) {
        __syncthreads();  // previous main-loop reads of d_s/w_s complete

        // --- dist tile: each thread owns one m-column, 16 rows ---
        const float kx = posb[(m0 + mmf) * 3 + 0];
        const float ky = posb[(m0 + mmf) * 3 + 1];
        const float kz = posb[(m0 + mmf) * 3 + 2];
#pragma unroll
        for (int i = 0; i < 16; i++) {
            int r = (i << 2) + rb;                 // same r across warp -> q_s broadcast
            float dx = q_s[r * 3 + 0] - kx;
            float dy = q_s[r * 3 + 1] - ky;
            float dz = q_s[r * 3 + 2] - kz;
            float sq = dx * dx + dy * dy + dz * dz;
            d_s[r * MT + mmf] = fsqrt_approx(sq);  // consecutive-lane columns: conflict-free
        }

        // --- W tile, XOR-swizzled columns so strided-f float4 reads are conflict-free ---
        const float4* wg = (const float4*)(W + (size_t)f_ld * NPT + m0 + mmc);
#pragma unroll
        for (int jj = 0; jj < 4; jj++) {
            float4 v = wg[jj];
            int col = (mmc + (jj << 2)) ^ swz;
            *(float4*)&w_s[f_ld * MT + col] = v;
        }
        __syncthreads();

        // --- main loop: 4x4 register outer product, packed over m pairs ---
#pragma unroll
        for (int mm = 0; mm < MT; mm += 4) {
            const int cw = mm ^ sw;
            ulonglong2 dv[4], wv[4];
#pragma unroll
            for (int j = 0; j < 4; j++)
                dv[j] = *(const ulonglong2*)&d_s[(r0 + j) * MT + mm];
#pragma unroll
            for (int i = 0; i < 4; i++)
                wv[i] = *(const ulonglong2*)&w_s[(f0 + i) * MT + cw];
#pragma unroll
            for (int j = 0; j < 4; j++)
#pragma unroll
                for (int i = 0; i < 4; i++) {
                    acc[j][i] = ffma2(dv[j].x, wv[i].x, acc[j][i]);
                    acc[j][i] = ffma2(dv[j].y, wv[i].y, acc[j][i]);
                }
        }
    }

    // --- epilogue: bias + LayerNorm (width-16 shfl; half-warp == one row) + SiLU ---
    const float4 bi = *(const float4*)(bias + f0);
    const float4 ga = *(const float4*)(gamma + f0);
    const float4 be = *(const float4*)(beta + f0);
    const float g[4]  = {ga.x, ga.y, ga.z, ga.w};
    const float bb[4] = {be.x, be.y, be.z, be.w};

#pragma unroll
    for (int j = 0; j < 4; j++) {
        float v[4];
#pragma unroll
        for (int i = 0; i < 4; i++) {
            unsigned long long a = acc[j][i];
            float lo = __uint_as_float((unsigned)(a & 0xffffffffULL));
            float hi = __uint_as_float((unsigned)(a >> 32));
            v[i] = lo + hi;
        }
        v[0] += bi.x; v[1] += bi.y; v[2] += bi.z; v[3] += bi.w;

        float s = v[0] + v[1] + v[2] + v[3];
#pragma unroll
        for (int off = 8; off >= 1; off >>= 1)
            s += __shfl_xor_sync(0xffffffffu, s, off, 16);
        float mean = s * (1.0f / 64.0f);

        float sv = 0.f;
#pragma unroll
        for (int i = 0; i < 4; i++) { float dd = v[i] - mean; sv += dd * dd; }
#pragma unroll
        for (int off = 8; off >= 1; off >>= 1)
            sv += __shfl_xor_sync(0xffffffffu, sv, off, 16);
        float rstd = rsqrtf(sv * (1.0f / 64.0f) + 1e-5f);

        float4 res;
        float* rp = (float*)&res;
#pragma unroll
        for (int i = 0; i < 4; i++) {
            float xn = (v[i] - mean) * rstd * g[i] + bb[i];
            rp[i] = xn / (1.0f + __expf(-xn));   // SiLU; xn->-inf gives -0, correct
        }
        int row = row0 + r0 + j;
        *(float4*)&out[((size_t)b * NPT + row) * FEATD + f0] = res;
    }
}

extern "C" void kernel_launch(void* const* d_in, const int* in_sizes, int n_in,
                              void* d_out, int out_size) {
    const float* pos   = (const float*)d_in[0];
    const float* W     = (const float*)d_in[1];
    const float* bias  = (const float*)d_in[2];
    const float* gamma = (const float*)d_in[3];
    const float* beta  = (const float*)d_in[4];
    float* out = (float*)d_out;
    dim3 grid(NPT / ROWS, BSZ);
    fused_relpos_kernel<<<grid, THREADS>>>(pos, W, bias, gamma, beta, out);
}

// round 4
// speedup vs baseline: 1.0098x; 1.0098x over previous
#include <cuda_runtime.h>

#define NPT    4096
#define BSZ    4
#define FEATD  64
#define MT     64
#define CROWS  128
#define THREADS 256
#define HALF_K 2048
#define NITER  (HALF_K / MT)   // 32

// smem layout (floats): q4[128]*4 | d_s[2][128][64] | w_s[2][64][64]
#define SM_Q_F    (CROWS * 4)                 // 512
#define SM_D_F    (2 * CROWS * MT)            // 16384
#define SM_W_F    (2 * FEATD * MT)            // 8192
#define SMEM_BYTES ((SM_Q_F + SM_D_F + SM_W_F) * 4)   // 100352

// Packed dual-fp32 FMA (sm_100+): lane0/lane1 accumulate even/odd-m partials.
__device__ __forceinline__ unsigned long long ffma2(unsigned long long a,
                                                    unsigned long long b,
                                                    unsigned long long c) {
    unsigned long long d;
    asm("fma.rn.f32x2 %0, %1, %2, %3;" : "=l"(d) : "l"(a), "l"(b), "l"(c));
    return d;
}

__device__ __forceinline__ float fsqrt_approx(float x) {
    float y;
    asm("sqrt.approx.f32 %0, %1;" : "=f"(y) : "f"(x));
    return y;  // sqrt.approx(+0) == +0: matches reference's safe-sqrt on the diagonal
}

__global__ __launch_bounds__(THREADS, 1)
void fused_relpos_kernel(const float* __restrict__ pos,
                         const float* __restrict__ W,
                         const float* __restrict__ bias,
                         const float* __restrict__ gamma,
                         const float* __restrict__ beta,
                         float* __restrict__ out) {
    extern __shared__ float sm[];
    float4* q4 = (float4*)sm;
    float*  dS = sm + SM_Q_F;
    float*  wS = sm + SM_Q_F + SM_D_F;

    const int t     = threadIdx.x;
    const int g     = t >> 7;        // k-group: m in [g*2048, g*2048+2048)
    const int local = t & 127;
    const int fx    = local & 7;     // feature group: feats fx*8 .. fx*8+7
    const int ry    = local >> 3;    // row group: rows ry*8 .. ry*8+7 (0..15)
    const int b     = blockIdx.y;
    const int row0  = blockIdx.x * CROWS;
    const float* posb = pos + (size_t)b * NPT * 3;

    // stage query positions as float4 (1 LDS.128 per row in the fill loop)
    if (t < CROWS) {
        const float* p = posb + (size_t)(row0 + t) * 3;
        q4[t] = make_float4(p[0], p[1], p[2], 0.0f);
    }

    float* dG = dS + g * CROWS * MT;
    float* wG = wS + g * FEATD * MT;

    // fill-phase constants
    const int mmf2  = (local & 31) * 2;     // this thread's 2 dist columns
    const int rb    = local >> 5;           // row phase (0..3), warp-uniform
    const int f_ld  = local >> 1;           // W feature row (0..63)
    const int wkey  = (f_ld >> 3) & 7;      // w_s write swizzle key
    const int cbase = (local & 1) * 8;      // 8 float4-chunks per thread
    // main-loop constants
    const int rbase = ry * 8;
    const int dkey  = ry & 7;               // d_s read swizzle key (lane-varying!)
    // dist write swizzle: key (r>>3)&7 varies per row below

    unsigned long long acc[8][8];
#pragma unroll
    for (int j = 0; j < 8; j++)
#pragma unroll
        for (int i = 0; i < 8; i++) acc[j][i] = 0ULL;

    for (int it = 0; it < NITER; it++) {
        const int m0 = g * HALF_K + it * MT;
        __syncthreads();   // previous main-loop reads of dG/wG complete

        // ---- dist tile fill: 2 columns x 128 rows per thread ----
        {
            const float* pk = posb + (size_t)(m0 + mmf2) * 3;
            const float k0x = pk[0], k0y = pk[1], k0z = pk[2];
            const float k1x = pk[3], k1y = pk[4], k1z = pk[5];
            const int chunk = mmf2 >> 2;
            const int sub   = mmf2 & 3;      // 0 or 2 within the chunk
#pragma unroll 4
            for (int i = 0; i < 32; i++) {
                const int r = i * 4 + rb;    // warp-uniform -> q4 broadcast
                const float4 q = q4[r];
                float dx = q.x - k0x, dy = q.y - k0y, dz = q.z - k0z;
                const float s0 = dx * dx + dy * dy + dz * dz;
                dx = q.x - k1x; dy = q.y - k1y; dz = q.z - k1z;
                const float s1 = dx * dx + dy * dy + dz * dz;
                float2 dv2 = make_float2(fsqrt_approx(s0), fsqrt_approx(s1));
                const int col = (((chunk ^ ((r >> 3) & 7)) << 2) | sub);
                *(float2*)&dG[r * MT + col] = dv2;
            }
        }

        // ---- W tile fill: 8 float4 chunks per thread, XOR-swizzled ----
        {
            const float4* wrow = (const float4*)(W + (size_t)f_ld * NPT + m0);
#pragma unroll
            for (int c = 0; c < 8; c++) {
                const int ch = cbase + c;
                float4 v = wrow[ch];
                *(float4*)&wG[f_ld * MT + ((ch ^ wkey) << 2)] = v;
            }
        }
        __syncthreads();

        // ---- main loop: 8x8 register outer product, packed over m pairs ----
#pragma unroll
        for (int mm4 = 0; mm4 < 16; mm4++) {
            const int cd = (mm4 ^ dkey) << 2;
            const int cw = (mm4 ^ fx) << 2;
            ulonglong2 dv[8];
#pragma unroll
            for (int j = 0; j < 8; j++)
                dv[j] = *(const ulonglong2*)&dG[(rbase + j) * MT + cd];
#pragma unroll
            for (int half = 0; half < 2; half++) {
                ulonglong2 wv[4];
#pragma unroll
                for (int i = 0; i < 4; i++)
                    wv[i] = *(const ulonglong2*)&wG[(fx * 8 + half * 4 + i) * MT + cw];
#pragma unroll
                for (int j = 0; j < 8; j++)
#pragma unroll
                    for (int i = 0; i < 4; i++) {
                        const int ii = half * 4 + i;
                        acc[j][ii] = ffma2(dv[j].x, wv[i].x, acc[j][ii]);
                        acc[j][ii] = ffma2(dv[j].y, wv[i].y, acc[j][ii]);
                    }
            }
        }
    }

    // ---- collapse f32x2 accumulators to scalars ----
    float v[8][8];
#pragma unroll
    for (int j = 0; j < 8; j++)
#pragma unroll
        for (int i = 0; i < 8; i++) {
            const unsigned long long a = acc[j][i];
            v[j][i] = __uint_as_float((unsigned)(a & 0xffffffffULL)) +
                      __uint_as_float((unsigned)(a >> 32));
        }

    // ---- combine the two k-groups through smem (reuse dS; pitch 65 = conflict-free) ----
    __syncthreads();
    if (g == 1) {
        float* cb = dS + local * 65;
#pragma unroll
        for (int j = 0; j < 8; j++)
#pragma unroll
            for (int i = 0; i < 8; i++) cb[j * 8 + i] = v[j][i];
    }
    __syncthreads();

    if (g == 0) {
        const float* cb = dS + local * 65;
#pragma unroll
        for (int j = 0; j < 8; j++)
#pragma unroll
            for (int i = 0; i < 8; i++) v[j][i] += cb[j * 8 + i];

        const int fb = fx * 8;
        const float4 bi0 = *(const float4*)(bias + fb);
        const float4 bi1 = *(const float4*)(bias + fb + 4);
        const float4 ga0 = *(const float4*)(gamma + fb);
        const float4 ga1 = *(const float4*)(gamma + fb + 4);
        const float4 be0 = *(const float4*)(beta + fb);
        const float4 be1 = *(const float4*)(beta + fb + 4);
        const float gg[8] = {ga0.x, ga0.y, ga0.z, ga0.w, ga1.x, ga1.y, ga1.z, ga1.w};
        const float bb[8] = {be0.x, be0.y, be0.z, be0.w, be1.x, be1.y, be1.z, be1.w};
        const float bs[8] = {bi0.x, bi0.y, bi0.z, bi0.w, bi1.x, bi1.y, bi1.z, bi1.w};

#pragma unroll
        for (int j = 0; j < 8; j++) {
            float x[8];
            float s = 0.0f;
#pragma unroll
            for (int i = 0; i < 8; i++) { x[i] = v[j][i] + bs[i]; s += x[i]; }
            // width-8 reductions: lanes fx=0..7 of the same ry group
#pragma unroll
            for (int off = 4; off >= 1; off >>= 1)
                s += __shfl_xor_sync(0xffffffffu, s, off, 8);
            const float mean = s * (1.0f / 64.0f);

            float sv = 0.0f;
#pragma unroll
            for (int i = 0; i < 8; i++) { const float d = x[i] - mean; sv += d * d; }
#pragma unroll
            for (int off = 4; off >= 1; off >>= 1)
                sv += __shfl_xor_sync(0xffffffffu, sv, off, 8);
            const float rstd = rsqrtf(sv * (1.0f / 64.0f) + 1e-5f);

            float4 r0, r1;
            float* rp = (float*)&r0;
#pragma unroll
            for (int i = 0; i < 4; i++) {
                const float xn = (x[i] - mean) * rstd * gg[i] + bb[i];
                rp[i] = xn / (1.0f + __expf(-xn));
            }
            rp = (float*)&r1;
#pragma unroll
            for (int i = 0; i < 4; i++) {
                const float xn = (x[4 + i] - mean) * rstd * gg[4 + i] + bb[4 + i];
                rp[i] = xn / (1.0f + __expf(-xn));
            }
            const int row = row0 + rbase + j;
            float* op = out + ((size_t)b * NPT + row) * FEATD + fb;
            *(float4*)op = r0;
            *(float4*)(op + 4) = r1;
        }
    }
}

extern "C" void kernel_launch(void* const* d_in, const int* in_sizes, int n_in,
                              void* d_out, int out_size) {
    const float* pos   = (const float*)d_in[0];
    const float* W     = (const float*)d_in[1];
    const float* bias  = (const float*)d_in[2];
    const float* gamma = (const float*)d_in[3];
    const float* beta  = (const float*)d_in[4];
    float* out = (float*)d_out;

    cudaFuncSetAttribute(fused_relpos_kernel,
                         cudaFuncAttributeMaxDynamicSharedMemorySize, SMEM_BYTES);

    dim3 grid(NPT / CROWS, BSZ);   // (32, 4) = 128 CTAs, one per SM
    fused_relpos_kernel<<<grid, THREADS, SMEM_BYTES>>>(pos, W, bias, gamma, beta, out);
}

// round 9
// speedup vs baseline: 1.9975x; 1.9781x over previous
#include <cuda_runtime.h>
#include <cuda_bf16.h>

#define NPT    4096
#define BSZ    4
#define FEATD  64
#define CROWS  128
#define KT     64
#define NCHUNK 64
#define THREADS 256

// dynamic smem byte offsets
#define OFF_Q    0u          // 128 x float4
#define OFF_LNP  2048u       // bias|gamma|beta (192 floats)
#define OFF_A    4096u       // [stage][hi/lo][128 rows][128B] = 4 x 16384
#define OFF_B    69632u      // [stage][hi/lo][ 64 rows][128B] = 4 x 8192
#define SMEM_TOTAL 102400u

#define SWZ(o) ((o) ^ (((o) >> 3) & 0x70u))

__device__ __forceinline__ unsigned sm_u32(const void* p) {
    unsigned a;
    asm("{ .reg .u64 t; cvta.to.shared.u64 t, %1; cvt.u32.u64 %0, t; }" : "=r"(a) : "l"(p));
    return a;
}
__device__ __forceinline__ float fsqrt_approx(float x) {
    float y; asm("sqrt.approx.f32 %0, %1;" : "=f"(y) : "f"(x)); return y;
}
__device__ __forceinline__ void ldsm4(unsigned* d, unsigned addr) {
    asm volatile("ldmatrix.sync.aligned.m8n8.x4.shared.b16 {%0,%1,%2,%3}, [%4];"
                 : "=r"(d[0]), "=r"(d[1]), "=r"(d[2]), "=r"(d[3]) : "r"(addr));
}
__device__ __forceinline__ void hmma(float* c, const unsigned* a, const unsigned* b) {
    asm volatile("mma.sync.aligned.m16n8k16.row.col.f32.bf16.bf16.f32 "
                 "{%0,%1,%2,%3}, {%4,%5,%6,%7}, {%8,%9}, {%0,%1,%2,%3};"
                 : "+f"(c[0]), "+f"(c[1]), "+f"(c[2]), "+f"(c[3])
                 : "r"(a[0]), "r"(a[1]), "r"(a[2]), "r"(a[3]), "r"(b[0]), "r"(b[1]));
}

__global__ __launch_bounds__(THREADS, 1)
void fused_relpos_hmma_kernel(const float* __restrict__ pos,
                              const float* __restrict__ W,
                              const float* __restrict__ bias,
                              const float* __restrict__ gamma,
                              const float* __restrict__ beta,
                              float* __restrict__ out) {
    extern __shared__ char smc[];
    const unsigned smb = sm_u32(smc);

    const int t    = threadIdx.x;
    const int wid  = t >> 5;
    const int lane = t & 31;
    const int b    = blockIdx.y;
    const int row0 = blockIdx.x * CROWS;
    const float* posb = pos + (size_t)b * NPT * 3;

    // ---- stage q (with trailing 0 pad) and LN params ----
    if (t < CROWS) {
        const float* p = posb + (size_t)(row0 + t) * 3;
        ((float4*)(smc + OFF_Q))[t] = make_float4(p[0], p[1], p[2], 0.0f);
    }
    if (t < 192) {
        float v = (t < 64) ? bias[t] : (t < 128) ? gamma[t - 64] : beta[t - 128];
        ((float*)(smc + OFF_LNP))[t] = v;
    }

    // ---- fill-phase constants ----
    const int pc = t & 31;            // dist: pair-columns 2pc, 2pc+1
    const int rA = t >> 5;            // dist: row phase (0..7) -> key rA
    const unsigned colA = ((((unsigned)(pc >> 2)) ^ (unsigned)rA) << 4) + (pc & 3) * 4;
    const int fW = t & 63;            // W: feature row
    const int hb = t >> 6;            // W: chunk pair base (chunks 2hb, 2hb+1)

    // ---- compute-phase constants (warp tiling: 4 M-warps x 2 N-warps) ----
    const int wm = wid >> 1, wn = wid & 1;
    const int ra0 = wm * 32 + (lane & 15);              // A rows (mt=0); mt=1 -> +16
    const int ca  = lane >> 4;
    const int ka  = ra0 & 7;
    const int rb0 = wn * 32 + (ca << 3) + (lane & 7);   // B rows (ntp=0); ntp=1 -> +16
    const int cb  = (lane >> 3) & 1;
    const int kb  = lane & 7;

    float acc[2][4][4];
#pragma unroll
    for (int mt = 0; mt < 2; mt++)
#pragma unroll
        for (int nt = 0; nt < 4; nt++)
#pragma unroll
            for (int k = 0; k < 4; k++) acc[mt][nt][k] = 0.0f;

    // ---- prefetch chunk-0 globals ----
    float k0x, k0y, k0z, k1x, k1y, k1z;
    float4 wv[4];
    {
        const float* pk = posb + (size_t)(2 * pc) * 3;
        k0x = pk[0]; k0y = pk[1]; k0z = pk[2]; k1x = pk[3]; k1y = pk[4]; k1z = pk[5];
        const float4* s0 = (const float4*)(W + (size_t)fW * NPT + hb * 16);
        wv[0] = s0[0]; wv[1] = s0[1]; wv[2] = s0[2]; wv[3] = s0[3];
    }
    __syncthreads();   // q/LNP visible

#pragma unroll 1
    for (int it = 0; it < NCHUNK; it++) {
        const int s = it & 1;
        const unsigned aHI = OFF_A + (unsigned)(s * 2 + 0) * 16384u;
        const unsigned aLO = OFF_A + (unsigned)(s * 2 + 1) * 16384u;
        const unsigned bHI = OFF_B + (unsigned)(s * 2 + 0) * 8192u;
        const unsigned bLO = OFF_B + (unsigned)(s * 2 + 1) * 8192u;

        // ---- A tile: dist hi/lo, 2 columns x 128 rows per thread ----
        {
            const float4* q4 = (const float4*)(smc + OFF_Q);
#pragma unroll
            for (int i = 0; i < 16; i++) {
                const int r = rA + i * 8;                 // warp-uniform -> q4 broadcast
                const float4 q = q4[r];
                float dx = q.x - k0x, dy = q.y - k0y, dz = q.z - k0z;
                const float s0 = dx * dx + dy * dy + dz * dz;
                dx = q.x - k1x; dy = q.y - k1y; dz = q.z - k1z;
                const float s1 = dx * dx + dy * dy + dz * dz;
                const float d0 = fsqrt_approx(s0), d1 = fsqrt_approx(s1);
                __nv_bfloat162 h = __floats2bfloat162_rn(d0, d1);
                const unsigned hu = *(const unsigned*)&h;
                const float h0 = __uint_as_float(hu << 16);
                const float h1 = __uint_as_float(hu & 0xffff0000u);
                __nv_bfloat162 l = __floats2bfloat162_rn(d0 - h0, d1 - h1);
                const unsigned off = (unsigned)(r * 128) + colA;
                *(unsigned*)(smc + aHI + off) = hu;
                *(unsigned*)(smc + aLO + off) = *(const unsigned*)&l;
            }
        }

        // ---- B tile: W hi/lo, rows of 8 floats -> one 16B chunk each ----
        {
#pragma unroll
            for (int cc = 0; cc < 2; cc++) {
                const float4 va = wv[cc * 2], vb = wv[cc * 2 + 1];
                __nv_bfloat162 h0 = __floats2bfloat162_rn(va.x, va.y);
                __nv_bfloat162 h1 = __floats2bfloat162_rn(va.z, va.w);
                __nv_bfloat162 h2 = __floats2bfloat162_rn(vb.x, vb.y);
                __nv_bfloat162 h3 = __floats2bfloat162_rn(vb.z, vb.w);
                __nv_bfloat162 l0 = __floats2bfloat162_rn(va.x - __bfloat162float(h0.x), va.y - __bfloat162float(h0.y));
                __nv_bfloat162 l1 = __floats2bfloat162_rn(va.z - __bfloat162float(h1.x), va.w - __bfloat162float(h1.y));
                __nv_bfloat162 l2 = __floats2bfloat162_rn(vb.x - __bfloat162float(h2.x), vb.y - __bfloat162float(h2.y));
                __nv_bfloat162 l3 = __floats2bfloat162_rn(vb.z - __bfloat162float(h3.x), vb.w - __bfloat162float(h3.y));
                uint4 uh, ul;
                uh.x = *(unsigned*)&h0; uh.y = *(unsigned*)&h1; uh.z = *(unsigned*)&h2; uh.w = *(unsigned*)&h3;
                ul.x = *(unsigned*)&l0; ul.y = *(unsigned*)&l1; ul.z = *(unsigned*)&l2; ul.w = *(unsigned*)&l3;
                const unsigned ch  = (unsigned)(hb * 2 + cc);
                const unsigned off = (unsigned)(fW * 128) + ((ch ^ (unsigned)(fW & 7)) << 4);
                *(uint4*)(smc + bHI + off) = uh;
                *(uint4*)(smc + bLO + off) = ul;
            }
        }

        // ---- prefetch next chunk's globals (registers only) ----
        if (it + 1 < NCHUNK) {
            const int m0n = (it + 1) * KT;
            const float* pk = posb + (size_t)(m0n + 2 * pc) * 3;
            k0x = pk[0]; k0y = pk[1]; k0z = pk[2]; k1x = pk[3]; k1y = pk[4]; k1z = pk[5];
            const float4* sn = (const float4*)(W + (size_t)fW * NPT + m0n + hb * 16);
            wv[0] = sn[0]; wv[1] = sn[1]; wv[2] = sn[2]; wv[3] = sn[3];
        }

        __syncthreads();   // tiles ready; also guarantees prior compute drained

        // ---- compute: per ktile load frags, 24 HMMA ----
#pragma unroll
        for (int kt = 0; kt < 4; kt++) {
            const unsigned cA = (((unsigned)((kt << 1) | ca) ^ (unsigned)ka) << 4);
            const unsigned cB = (((unsigned)((kt << 1) | cb) ^ (unsigned)kb) << 4);
            unsigned ah[8], al[8], bh[8], bl[8];
            ldsm4(ah,     smb + aHI + (unsigned)(ra0 * 128) + cA);
            ldsm4(ah + 4, smb + aHI + (unsigned)((ra0 + 16) * 128) + cA);
            ldsm4(al,     smb + aLO + (unsigned)(ra0 * 128) + cA);
            ldsm4(al + 4, smb + aLO + (unsigned)((ra0 + 16) * 128) + cA);
            ldsm4(bh,     smb + bHI + (unsigned)(rb0 * 128) + cB);
            ldsm4(bh + 4, smb + bHI + (unsigned)((rb0 + 16) * 128) + cB);
            ldsm4(bl,     smb + bLO + (unsigned)(rb0 * 128) + cB);
            ldsm4(bl + 4, smb + bLO + (unsigned)((rb0 + 16) * 128) + cB);
#pragma unroll
            for (int mt = 0; mt < 2; mt++)
#pragma unroll
                for (int nt = 0; nt < 4; nt++) {
                    float* c = acc[mt][nt];
                    hmma(c, ah + 4 * mt, bh + nt * 2);
                    hmma(c, al + 4 * mt, bh + nt * 2);
                    hmma(c, ah + 4 * mt, bl + nt * 2);
                }
        }
    }

    // ---- epilogue: accumulators -> smem (pitch 65), then per-row LN + SiLU ----
    __syncthreads();   // all warps done reading tiles before we overwrite them
    float* xs = (float*)(smc + OFF_A);
    {
        const int qr = lane >> 2, qc = (lane & 3) * 2;
#pragma unroll
        for (int mt = 0; mt < 2; mt++)
#pragma unroll
            for (int nt = 0; nt < 4; nt++) {
                const int r0r = wm * 32 + mt * 16 + qr;
                const int ff  = wn * 32 + nt * 8 + qc;
                xs[r0r * 65 + ff]           = acc[mt][nt][0];
                xs[r0r * 65 + ff + 1]       = acc[mt][nt][1];
                xs[(r0r + 8) * 65 + ff]     = acc[mt][nt][2];
                xs[(r0r + 8) * 65 + ff + 1] = acc[mt][nt][3];
            }
    }
    __syncthreads();

    if (t < CROWS) {
        const float* lnp = (const float*)(smc + OFF_LNP);
        const float* xr  = xs + t * 65;
        float x[64];
        float sum = 0.0f;
#pragma unroll
        for (int f = 0; f < 64; f++) { x[f] = xr[f] + lnp[f]; sum += x[f]; }
        const float mean = sum * (1.0f / 64.0f);
        float var = 0.0f;
#pragma unroll
        for (int f = 0; f < 64; f++) { const float d = x[f] - mean; var += d * d; }
        const float rstd = rsqrtf(var * (1.0f / 64.0f) + 1e-5f);

        float* op = out + ((size_t)b * NPT + row0 + t) * FEATD;
#pragma unroll
        for (int f = 0; f < 64; f += 4) {
            float4 r;
            float* rp = (float*)&r;
#pragma unroll
            for (int k = 0; k < 4; k++) {
                const float xn = (x[f + k] - mean) * rstd * lnp[64 + f + k] + lnp[128 + f + k];
                rp[k] = xn / (1.0f + __expf(-xn));
            }
            *(float4*)(op + f) = r;
        }
    }
}

extern "C" void kernel_launch(void* const* d_in, const int* in_sizes, int n_in,
                              void* d_out, int out_size) {
    const float* pos   = (const float*)d_in[0];
    const float* W     = (const float*)d_in[1];
    const float* bias  = (const float*)d_in[2];
    const float* gamma = (const float*)d_in[3];
    const float* beta  = (const float*)d_in[4];
    float* out = (float*)d_out;

    cudaFuncSetAttribute(fused_relpos_hmma_kernel,
                         cudaFuncAttributeMaxDynamicSharedMemorySize, SMEM_TOTAL);

    dim3 grid(NPT / CROWS, BSZ);   // (32, 4) = 128 CTAs, 1 per SM
    fused_relpos_hmma_kernel<<<grid, THREADS, SMEM_TOTAL>>>(pos, W, bias, gamma, beta, out);
}

// round 10
// speedup vs baseline: 2.4203x; 1.2117x over previous
#include <cuda_runtime.h>
#include <cuda_fp16.h>

#define NPT    4096
#define BSZ    4
#define FEATD  64
#define CROWS  128
#define KT     64
#define NCHUNK 64
#define THREADS 256

// dynamic smem byte offsets
#define OFF_Q    0u          // 128 x float4
#define OFF_LNP  2048u       // bias|gamma|beta (192 floats)
#define OFF_A    4096u       // [stage][128 rows][128B]  (dist, single fp16)
#define OFF_B    36864u      // [stage][hi/lo][64 rows][128B]
#define SMEM_TOTAL 69632u

__device__ __forceinline__ unsigned sm_u32(const void* p) {
    unsigned a;
    asm("{ .reg .u64 t; cvta.to.shared.u64 t, %1; cvt.u32.u64 %0, t; }" : "=r"(a) : "l"(p));
    return a;
}
__device__ __forceinline__ float fsqrt_approx(float x) {
    float y; asm("sqrt.approx.f32 %0, %1;" : "=f"(y) : "f"(x)); return y;
}
__device__ __forceinline__ void ldsm4(unsigned* d, unsigned addr) {
    asm volatile("ldmatrix.sync.aligned.m8n8.x4.shared.b16 {%0,%1,%2,%3}, [%4];"
                 : "=r"(d[0]), "=r"(d[1]), "=r"(d[2]), "=r"(d[3]) : "r"(addr));
}
__device__ __forceinline__ void hmma16(float* c, const unsigned* a, const unsigned* b) {
    asm volatile("mma.sync.aligned.m16n8k16.row.col.f32.f16.f16.f32 "
                 "{%0,%1,%2,%3}, {%4,%5,%6,%7}, {%8,%9}, {%0,%1,%2,%3};"
                 : "+f"(c[0]), "+f"(c[1]), "+f"(c[2]), "+f"(c[3])
                 : "r"(a[0]), "r"(a[1]), "r"(a[2]), "r"(a[3]), "r"(b[0]), "r"(b[1]));
}

// dist tile: 2 columns x 128 rows per thread, single fp16
__device__ __forceinline__ void fill_A(char* smc, unsigned aS,
                                       float k0x, float k0y, float k0z,
                                       float k1x, float k1y, float k1z,
                                       unsigned colA, int rA) {
    const float4* q4 = (const float4*)(smc + OFF_Q);
#pragma unroll
    for (int i = 0; i < 16; i++) {
        const int r = rA + i * 8;                 // warp-uniform -> q4 broadcast
        const float4 q = q4[r];
        float dx = q.x - k0x, dy = q.y - k0y, dz = q.z - k0z;
        const float s0 = dx * dx + dy * dy + dz * dz;
        dx = q.x - k1x; dy = q.y - k1y; dz = q.z - k1z;
        const float s1 = dx * dx + dy * dy + dz * dz;
        __half2 h = __floats2half2_rn(fsqrt_approx(s0), fsqrt_approx(s1));
        *(unsigned*)(smc + aS + (unsigned)(r * 128) + colA) = *(unsigned*)&h;
    }
}

// W tile: hi/lo fp16 split, 2 x 16B chunks per thread
__device__ __forceinline__ void fill_B(char* smc, unsigned bHI, unsigned bLO,
                                       const float4* wv, int fW, int hb) {
#pragma unroll
    for (int cc = 0; cc < 2; cc++) {
        const float4 va = wv[cc * 2], vb = wv[cc * 2 + 1];
        __half2 h0 = __floats2half2_rn(va.x, va.y);
        __half2 h1 = __floats2half2_rn(va.z, va.w);
        __half2 h2 = __floats2half2_rn(vb.x, vb.y);
        __half2 h3 = __floats2half2_rn(vb.z, vb.w);
        __half2 l0 = __floats2half2_rn(va.x - __low2float(h0), va.y - __high2float(h0));
        __half2 l1 = __floats2half2_rn(va.z - __low2float(h1), va.w - __high2float(h1));
        __half2 l2 = __floats2half2_rn(vb.x - __low2float(h2), vb.y - __high2float(h2));
        __half2 l3 = __floats2half2_rn(vb.z - __low2float(h3), vb.w - __high2float(h3));
        uint4 uh, ul;
        uh.x = *(unsigned*)&h0; uh.y = *(unsigned*)&h1; uh.z = *(unsigned*)&h2; uh.w = *(unsigned*)&h3;
        ul.x = *(unsigned*)&l0; ul.y = *(unsigned*)&l1; ul.z = *(unsigned*)&l2; ul.w = *(unsigned*)&l3;
        const unsigned ch  = (unsigned)(hb * 2 + cc);
        const unsigned off = (unsigned)(fW * 128) + ((ch ^ (unsigned)(fW & 7)) << 4);
        *(uint4*)(smc + bHI + off) = uh;
        *(uint4*)(smc + bLO + off) = ul;
    }
}

__global__ __launch_bounds__(THREADS, 1)
void fused_relpos_hmma_kernel(const float* __restrict__ pos,
                              const float* __restrict__ W,
                              const float* __restrict__ bias,
                              const float* __restrict__ gamma,
                              const float* __restrict__ beta,
                              float* __restrict__ out) {
    extern __shared__ char smc[];
    const unsigned smb = sm_u32(smc);

    const int t    = threadIdx.x;
    const int wid  = t >> 5;
    const int lane = t & 31;
    const int b    = blockIdx.y;
    const int row0 = blockIdx.x * CROWS;
    const float* posb = pos + (size_t)b * NPT * 3;

    // ---- stage q and LN params ----
    if (t < CROWS) {
        const float* p = posb + (size_t)(row0 + t) * 3;
        ((float4*)(smc + OFF_Q))[t] = make_float4(p[0], p[1], p[2], 0.0f);
    }
    if (t < 192) {
        float v = (t < 64) ? bias[t] : (t < 128) ? gamma[t - 64] : beta[t - 128];
        ((float*)(smc + OFF_LNP))[t] = v;
    }

    // ---- fill-phase constants ----
    const int pc = t & 31;            // dist: pair-columns 2pc, 2pc+1
    const int rA = t >> 5;            // dist: row phase (0..7)
    const unsigned colA = ((((unsigned)(pc >> 2)) ^ (unsigned)rA) << 4) + (pc & 3) * 4;
    const int fW = t & 63;            // W: feature row
    const int hb = t >> 6;            // W: chunk pair base

    // ---- compute-phase constants (4 M-warps x 2 N-warps) ----
    const int wm = wid >> 1, wn = wid & 1;
    const int ra0 = wm * 32 + (lane & 15);
    const int ca  = lane >> 4;
    const int ka  = ra0 & 7;
    const int rb0 = wn * 32 + (ca << 3) + (lane & 7);
    const int cb  = (lane >> 3) & 1;
    const int kb  = lane & 7;

    float acc[2][4][4];
#pragma unroll
    for (int mt = 0; mt < 2; mt++)
#pragma unroll
        for (int nt = 0; nt < 4; nt++)
#pragma unroll
            for (int k = 0; k < 4; k++) acc[mt][nt][k] = 0.0f;

    // ---- prefetch chunk-0 globals, fill stage 0, prefetch chunk-1 ----
    float k0x, k0y, k0z, k1x, k1y, k1z;
    float4 wv[4];
    {
        const float* pk = posb + (size_t)(2 * pc) * 3;
        k0x = pk[0]; k0y = pk[1]; k0z = pk[2]; k1x = pk[3]; k1y = pk[4]; k1z = pk[5];
        const float4* s0 = (const float4*)(W + (size_t)fW * NPT + hb * 16);
        wv[0] = s0[0]; wv[1] = s0[1]; wv[2] = s0[2]; wv[3] = s0[3];
    }
    __syncthreads();   // q visible before fill_A reads it
    fill_A(smc, OFF_A, k0x, k0y, k0z, k1x, k1y, k1z, colA, rA);
    fill_B(smc, OFF_B, OFF_B + 8192u, wv, fW, hb);
    {
        const float* pk = posb + (size_t)(KT + 2 * pc) * 3;
        k0x = pk[0]; k0y = pk[1]; k0z = pk[2]; k1x = pk[3]; k1y = pk[4]; k1z = pk[5];
        const float4* sn = (const float4*)(W + (size_t)fW * NPT + KT + hb * 16);
        wv[0] = sn[0]; wv[1] = sn[1]; wv[2] = sn[2]; wv[3] = sn[3];
    }
    __syncthreads();

#pragma unroll 1
    for (int it = 0; it < NCHUNK; it++) {
        const int s = it & 1;
        const unsigned aS  = OFF_A + (unsigned)s * 16384u;
        const unsigned bHI = OFF_B + (unsigned)s * 16384u;
        const unsigned bLO = bHI + 8192u;

        // ---- compute(it): tensor stream issues first ----
#pragma unroll
        for (int kt = 0; kt < 4; kt++) {
            const unsigned cA = (((unsigned)((kt << 1) | ca) ^ (unsigned)ka) << 4);
            const unsigned cB = (((unsigned)((kt << 1) | cb) ^ (unsigned)kb) << 4);
            unsigned a[8], bh[8], bl[8];
            ldsm4(a,      smb + aS  + (unsigned)(ra0 * 128) + cA);
            ldsm4(a + 4,  smb + aS  + (unsigned)((ra0 + 16) * 128) + cA);
            ldsm4(bh,     smb + bHI + (unsigned)(rb0 * 128) + cB);
            ldsm4(bh + 4, smb + bHI + (unsigned)((rb0 + 16) * 128) + cB);
            ldsm4(bl,     smb + bLO + (unsigned)(rb0 * 128) + cB);
            ldsm4(bl + 4, smb + bLO + (unsigned)((rb0 + 16) * 128) + cB);
#pragma unroll
            for (int mt = 0; mt < 2; mt++)
#pragma unroll
                for (int nt = 0; nt < 4; nt++) {
                    float* c = acc[mt][nt];
                    hmma16(c, a + 4 * mt, bh + nt * 2);
                    hmma16(c, a + 4 * mt, bl + nt * 2);
                }
        }

        // ---- fill(it+1) into stage s^1 (overlaps other warps' compute) ----
        if (it + 1 < NCHUNK) {
            const unsigned aN  = OFF_A + (unsigned)(s ^ 1) * 16384u;
            const unsigned bHN = OFF_B + (unsigned)(s ^ 1) * 16384u;
            fill_A(smc, aN, k0x, k0y, k0z, k1x, k1y, k1z, colA, rA);
            fill_B(smc, bHN, bHN + 8192u, wv, fW, hb);
            if (it + 2 < NCHUNK) {
                const int m0n = (it + 2) * KT;
                const float* pk = posb + (size_t)(m0n + 2 * pc) * 3;
                k0x = pk[0]; k0y = pk[1]; k0z = pk[2]; k1x = pk[3]; k1y = pk[4]; k1z = pk[5];
                const float4* sn = (const float4*)(W + (size_t)fW * NPT + m0n + hb * 16);
                wv[0] = sn[0]; wv[1] = sn[1]; wv[2] = sn[2]; wv[3] = sn[3];
            }
        }
        __syncthreads();
    }

    // ---- epilogue: accumulators -> smem (pitch 65), per-row LN + SiLU ----
    float* xs = (float*)(smc + OFF_A);
    {
        const int qr = lane >> 2, qc = (lane & 3) * 2;
#pragma unroll
        for (int mt = 0; mt < 2; mt++)
#pragma unroll
            for (int nt = 0; nt < 4; nt++) {
                const int r0r = wm * 32 + mt * 16 + qr;
                const int ff  = wn * 32 + nt * 8 + qc;
                xs[r0r * 65 + ff]           = acc[mt][nt][0];
                xs[r0r * 65 + ff + 1]       = acc[mt][nt][1];
                xs[(r0r + 8) * 65 + ff]     = acc[mt][nt][2];
                xs[(r0r + 8) * 65 + ff + 1] = acc[mt][nt][3];
            }
    }
    __syncthreads();

    if (t < CROWS) {
        const float* lnp = (const float*)(smc + OFF_LNP);
        const float* xr  = xs + t * 65;
        float x[64];
        float sum = 0.0f;
#pragma unroll
        for (int f = 0; f < 64; f++) { x[f] = xr[f] + lnp[f]; sum += x[f]; }
        const float mean = sum * (1.0f / 64.0f);
        float var = 0.0f;
#pragma unroll
        for (int f = 0; f < 64; f++) { const float d = x[f] - mean; var += d * d; }
        const float rstd = rsqrtf(var * (1.0f / 64.0f) + 1e-5f);

        float* op = out + ((size_t)b * NPT + row0 + t) * FEATD;
#pragma unroll
        for (int f = 0; f < 64; f += 4) {
            float4 r;
            float* rp = (float*)&r;
#pragma unroll
            for (int k = 0; k < 4; k++) {
                const float xn = (x[f + k] - mean) * rstd * lnp[64 + f + k] + lnp[128 + f + k];
                rp[k] = xn / (1.0f + __expf(-xn));
            }
            *(float4*)(op + f) = r;
        }
    }
}

extern "C" void kernel_launch(void* const* d_in, const int* in_sizes, int n_in,
                              void* d_out, int out_size) {
    const float* pos   = (const float*)d_in[0];
    const float* W     = (const float*)d_in[1];
    const float* bias  = (const float*)d_in[2];
    const float* gamma = (const float*)d_in[3];
    const float* beta  = (const float*)d_in[4];
    float* out = (float*)d_out;

    cudaFuncSetAttribute(fused_relpos_hmma_kernel,
                         cudaFuncAttributeMaxDynamicSharedMemorySize, SMEM_TOTAL);

    dim3 grid(NPT / CROWS, BSZ);   // (32, 4) = 128 CTAs, 1 per SM
    fused_relpos_hmma_kernel<<<grid, THREADS, SMEM_TOTAL>>>(pos, W, bias, gamma, beta, out);
}